// round 1
// baseline (speedup 1.0000x reference)
#include <cuda_runtime.h>
#include <math.h>

// Problem shape (fixed by reference)
#define NB 32
#define NT 20
#define NH 64
#define NW 64
#define HW (NH * NW)            // 4096
#define NTILES (NB * NT)        // 640
#define NTOT ((float)(NB * NT * NH * NW))  // 2621440
#define EPS_V 1e-8f

#define SPARSITY_W 0.8f
#define CONC_W     1.5f
#define COORD_W    1.0f
#define BG_W       0.1f

__device__ float g_tile_contrib[NTILES];

// One CTA per (b,t) tile. 256 threads, 16 px/thread.
__global__ __launch_bounds__(256)
void tile_loss_kernel(const float* __restrict__ pred,
                      const float* __restrict__ tgt) {
    __shared__ float sp[HW];           // sigmoid(pred) for the tile (16 KB)
    __shared__ float warp_red[8][10];  // per-warp partials
    __shared__ float tot[10];          // block totals

    const int tile = blockIdx.x;
    const float* __restrict__ P = pred + (size_t)tile * HW;
    const float* __restrict__ T = tgt  + (size_t)tile * HW;

    const int tid  = threadIdx.x;
    const int lane = tid & 31;
    const int wid  = tid >> 5;

    float S = 0.f, Ts = 0.f, mx = 0.f;
    float pxs = 0.f, pys = 0.f, txs = 0.f, tys = 0.f;
    float foc = 0.f, bg = 0.f;

    #pragma unroll 4
    for (int j = tid; j < HW; j += 256) {
        float x = P[j];
        float t = T[j];
        float p = 1.f / (1.f + expf(-x));
        sp[j] = p;
        float xx = (float)(j & 63);
        float yy = (float)(j >> 6);
        S  += p;       Ts += t;
        mx  = fmaxf(mx, p);
        pxs += p * xx; pys += p * yy;
        txs += t * xx; tys += t * yy;
        // stable BCE with logits
        float bce = fmaxf(x, 0.f) - x * t + log1pf(expf(-fabsf(x)));
        float pt  = (t == 1.f) ? p : (1.f - p);
        float om  = 1.f - pt;
        foc += om * om * bce;          // FOCAL_ALPHA=1, GAMMA=2
        if (t == 0.f) bg += p * p;     // background MSE term
    }

    // warp-level reduction (8 sums + 1 max)
    const unsigned FULL = 0xffffffffu;
    #pragma unroll
    for (int o = 16; o; o >>= 1) {
        S   += __shfl_xor_sync(FULL, S,   o);
        Ts  += __shfl_xor_sync(FULL, Ts,  o);
        pxs += __shfl_xor_sync(FULL, pxs, o);
        pys += __shfl_xor_sync(FULL, pys, o);
        txs += __shfl_xor_sync(FULL, txs, o);
        tys += __shfl_xor_sync(FULL, tys, o);
        foc += __shfl_xor_sync(FULL, foc, o);
        bg  += __shfl_xor_sync(FULL, bg,  o);
        mx   = fmaxf(mx, __shfl_xor_sync(FULL, mx, o));
    }
    if (lane == 0) {
        warp_red[wid][0] = S;   warp_red[wid][1] = Ts;
        warp_red[wid][2] = pxs; warp_red[wid][3] = pys;
        warp_red[wid][4] = txs; warp_red[wid][5] = tys;
        warp_red[wid][6] = foc; warp_red[wid][7] = bg;
        warp_red[wid][8] = mx;
    }
    __syncthreads();
    if (tid == 0) {
        float a0=0,a1=0,a2=0,a3=0,a4=0,a5=0,a6=0,a7=0,a8=0;
        #pragma unroll
        for (int w = 0; w < 8; w++) {
            a0 += warp_red[w][0]; a1 += warp_red[w][1];
            a2 += warp_red[w][2]; a3 += warp_red[w][3];
            a4 += warp_red[w][4]; a5 += warp_red[w][5];
            a6 += warp_red[w][6]; a7 += warp_red[w][7];
            a8  = fmaxf(a8, warp_red[w][8]);
        }
        tot[0]=a0; tot[1]=a1; tot[2]=a2; tot[3]=a3; tot[4]=a4;
        tot[5]=a5; tot[6]=a6; tot[7]=a7; tot[8]=a8;
    }
    __syncthreads();

    // second pass: entropy over normalized p (smem only)
    float Sfull = tot[0];
    float inv = 1.f / (Sfull + EPS_V);
    float ent = 0.f;
    #pragma unroll 4
    for (int j = tid; j < HW; j += 256) {
        float q = sp[j] * inv;
        ent -= q * logf(q + EPS_V);
    }
    #pragma unroll
    for (int o = 16; o; o >>= 1)
        ent += __shfl_xor_sync(FULL, ent, o);
    if (lane == 0) warp_red[wid][9] = ent;
    __syncthreads();

    if (tid == 0) {
        float e = 0.f;
        #pragma unroll
        for (int w = 0; w < 8; w++) e += warp_red[w][9];

        float Sv  = tot[0], Tv = tot[1];
        float ps  = Sv + EPS_V, ts = Tv + EPS_V;
        float px  = tot[2] / ps, py = tot[3] / ps;
        float tx  = tot[4] / ts, ty = tot[5] / ts;
        float dx  = px - tx, dy = py - ty;
        float coord = sqrtf(dx * dx + dy * dy);
        float conc  = 1.f - tot[8];

        float contrib =
            (tot[6] + BG_W * tot[7]) * (1.f / NTOT) +
            (SPARSITY_W * e + CONC_W * conc + COORD_W * coord) * (1.f / (float)NTILES);
        g_tile_contrib[tile] = contrib;
    }
}

// Reduce the 640 per-tile contributions deterministically.
__global__ __launch_bounds__(256)
void finalize_kernel(float* __restrict__ out) {
    __shared__ float warp_red[8];
    const int tid  = threadIdx.x;
    const int lane = tid & 31;
    const int wid  = tid >> 5;

    float v = 0.f;
    for (int i = tid; i < NTILES; i += 256)
        v += g_tile_contrib[i];

    const unsigned FULL = 0xffffffffu;
    #pragma unroll
    for (int o = 16; o; o >>= 1)
        v += __shfl_xor_sync(FULL, v, o);
    if (lane == 0) warp_red[wid] = v;
    __syncthreads();
    if (tid == 0) {
        float s = 0.f;
        #pragma unroll
        for (int w = 0; w < 8; w++) s += warp_red[w];
        out[0] = s;
    }
}

extern "C" void kernel_launch(void* const* d_in, const int* in_sizes, int n_in,
                              void* d_out, int out_size) {
    const float* pred = (const float*)d_in[0];
    const float* tgt  = (const float*)d_in[1];
    float* out = (float*)d_out;
    tile_loss_kernel<<<NTILES, 256>>>(pred, tgt);
    finalize_kernel<<<1, 256>>>(out);
}

// round 2
// speedup vs baseline: 1.7987x; 1.7987x over previous
#include <cuda_runtime.h>
#include <math.h>

#define NH 64
#define NW 64
#define HW 4096
#define NTILES 640
#define NTOT_F 2621440.0f
#define EPS_V 1e-8f

#define SPARSITY_W 0.8f
#define CONC_W     1.5f
#define COORD_W    1.0f
#define BG_W       0.1f

__device__ float g_tile_contrib[NTILES];
__device__ unsigned int g_done = 0;

__device__ __forceinline__ float fast_tanh(float x) {
    float r;
    asm("tanh.approx.f32 %0, %1;" : "=f"(r) : "f"(x));
    return r;
}

// One CTA per (b,t) tile: 256 threads, 16 px/thread (4 float4 per input).
// Single pass computes all 10 tile statistics; last finished CTA does the
// final 640-element reduction (fixed order -> deterministic).
__global__ __launch_bounds__(256, 4)
void loss_kernel(const float4* __restrict__ pred,
                 const float4* __restrict__ tgt,
                 float* __restrict__ out) {
    __shared__ float warp_red[8][10];
    __shared__ bool is_last;

    const int tile = blockIdx.x;
    const float4* __restrict__ P = pred + (size_t)tile * (HW / 4);
    const float4* __restrict__ T = tgt  + (size_t)tile * (HW / 4);

    const int tid  = threadIdx.x;
    const int lane = tid & 31;
    const int wid  = tid >> 5;

    float S = 0.f, Ts = 0.f, mx = 0.f;
    float pxs = 0.f, pys = 0.f, txs = 0.f, tys = 0.f;
    float foc = 0.f, bg = 0.f, plog = 0.f;

    #pragma unroll
    for (int k = 0; k < 4; k++) {
        const int v = tid + k * 256;       // float4 index within tile [0,1024)
        float4 x4 = P[v];
        float4 t4 = T[v];
        const int j0 = v * 4;
        float xs[4] = {x4.x, x4.y, x4.z, x4.w};
        float tv[4] = {t4.x, t4.y, t4.z, t4.w};
        #pragma unroll
        for (int c = 0; c < 4; c++) {
            float x = xs[c];
            float t = tv[c];
            const int j = j0 + c;
            const float xx = (float)(j & 63);
            const float yy = (float)(j >> 6);

            // sigmoid via HW tanh: p = 0.5*tanh(x/2)+0.5
            float p  = fmaf(0.5f, fast_tanh(0.5f * x), 0.5f);
            float pm = fmaxf(p, 1.f - p);          // sigmoid(|x|)
            float lp = __logf(pm);                 // log sigmoid(|x|)  (<=0)
            // log p = min(x,0) + log sigmoid(|x|)
            float logp = fminf(x, 0.f) + lp;
            // stable BCE: max(x,0) - x*t + log1p(exp(-|x|)) ; log1p term = -lp
            float bce = fmaxf(x, 0.f) - x * t - lp;
            // om = 1 - p_t : t=1 -> 1-p, t=0 -> p  (t is exactly 0/1)
            float om = fmaf(-2.f * t, p, t + p);
            foc  = fmaf(om * om, bce, foc);
            bg   = fmaf((1.f - t) * p, p, bg);
            plog = fmaf(p, logp, plog);
            S  += p;  Ts += t;
            mx  = fmaxf(mx, p);
            pxs = fmaf(p, xx, pxs);  pys = fmaf(p, yy, pys);
            txs = fmaf(t, xx, txs);  tys = fmaf(t, yy, tys);
        }
    }

    // warp butterfly reduction of 9 sums + 1 max
    const unsigned FULL = 0xffffffffu;
    #pragma unroll
    for (int o = 16; o; o >>= 1) {
        S    += __shfl_xor_sync(FULL, S,    o);
        Ts   += __shfl_xor_sync(FULL, Ts,   o);
        pxs  += __shfl_xor_sync(FULL, pxs,  o);
        pys  += __shfl_xor_sync(FULL, pys,  o);
        txs  += __shfl_xor_sync(FULL, txs,  o);
        tys  += __shfl_xor_sync(FULL, tys,  o);
        foc  += __shfl_xor_sync(FULL, foc,  o);
        bg   += __shfl_xor_sync(FULL, bg,   o);
        plog += __shfl_xor_sync(FULL, plog, o);
        mx    = fmaxf(mx, __shfl_xor_sync(FULL, mx, o));
    }
    if (lane == 0) {
        warp_red[wid][0] = S;    warp_red[wid][1] = Ts;
        warp_red[wid][2] = pxs;  warp_red[wid][3] = pys;
        warp_red[wid][4] = txs;  warp_red[wid][5] = tys;
        warp_red[wid][6] = foc;  warp_red[wid][7] = bg;
        warp_red[wid][8] = plog; warp_red[wid][9] = mx;
    }
    __syncthreads();

    if (tid == 0) {
        float a0=0,a1=0,a2=0,a3=0,a4=0,a5=0,a6=0,a7=0,a8=0,a9=0;
        #pragma unroll
        for (int w = 0; w < 8; w++) {
            a0 += warp_red[w][0]; a1 += warp_red[w][1];
            a2 += warp_red[w][2]; a3 += warp_red[w][3];
            a4 += warp_red[w][4]; a5 += warp_red[w][5];
            a6 += warp_red[w][6]; a7 += warp_red[w][7];
            a8 += warp_red[w][8]; a9  = fmaxf(a9, warp_red[w][9]);
        }
        float Sp  = a0 + EPS_V;
        float inv = 1.f / Sp;
        // entropy: -sum q*log(q+eps) ~= inv*(S*log(S+eps) - sum p*log p)
        float ent = inv * (a0 * logf(Sp) - a8);
        float ts  = a1 + EPS_V;
        float px  = a2 * inv, py = a3 * inv;
        float tx  = a4 / ts,  ty = a5 / ts;
        float dx  = px - tx,  dy = py - ty;
        float coord = sqrtf(dx * dx + dy * dy);
        float conc  = 1.f - a9;

        g_tile_contrib[tile] =
            (a6 + BG_W * a7) * (1.f / NTOT_F) +
            (SPARSITY_W * ent + CONC_W * conc + COORD_W * coord) * (1.f / (float)NTILES);

        __threadfence();
        unsigned r = atomicAdd(&g_done, 1u);
        is_last = (r == NTILES - 1);
    }
    __syncthreads();

    if (is_last) {
        // deterministic final reduction over the 640 tile contributions
        float v = 0.f;
        for (int i = tid; i < NTILES; i += 256)
            v += g_tile_contrib[i];
        #pragma unroll
        for (int o = 16; o; o >>= 1)
            v += __shfl_xor_sync(FULL, v, o);
        if (lane == 0) warp_red[wid][0] = v;
        __syncthreads();
        if (tid == 0) {
            float s = 0.f;
            #pragma unroll
            for (int w = 0; w < 8; w++) s += warp_red[w][0];
            out[0] = s;
            g_done = 0;   // reset for next graph replay
        }
    }
}

extern "C" void kernel_launch(void* const* d_in, const int* in_sizes, int n_in,
                              void* d_out, int out_size) {
    const float4* pred = (const float4*)d_in[0];
    const float4* tgt  = (const float4*)d_in[1];
    float* out = (float*)d_out;
    loss_kernel<<<NTILES, 256>>>(pred, tgt, out);
}

// round 4
// speedup vs baseline: 2.5268x; 1.4048x over previous
#include <cuda_runtime.h>
#include <math.h>

#define HW 4096
#define NTILES 640
#define NTOT_F 2621440.0f
#define EPS_V 1e-8f

#define SPARSITY_W 0.8f
#define CONC_W     1.5f
#define COORD_W    1.0f
#define BG_W       0.1f

__device__ float g_tile_contrib[NTILES];
__device__ unsigned int g_done = 0;

__device__ __forceinline__ float fast_tanh(float x) {
    float r;
    asm("tanh.approx.f32 %0, %1;" : "=f"(r) : "f"(x));
    return r;
}

// One CTA per (b,t) tile: 256 threads, 16 px/thread (4 float4 groups).
__global__ __launch_bounds__(256, 4)
void loss_kernel(const float4* __restrict__ pred,
                 const float4* __restrict__ tgt,
                 float* __restrict__ out) {
    __shared__ float warp_red[8][10];
    __shared__ bool is_last;

    const int tile = blockIdx.x;
    const float4* __restrict__ P = pred + (size_t)tile * (HW / 4);
    const float4* __restrict__ T = tgt  + (size_t)tile * (HW / 4);

    const int tid  = threadIdx.x;
    const int lane = tid & 31;
    const int wid  = tid >> 5;

    // geometric invariants of this thread's 4 groups:
    //   element j = 4*(tid + 256k) + c  ->  col = ((4*tid)&63) + c (k-invariant)
    //                                       row = (tid>>4) + 16*k
    const float c0f = (float)((tid * 4) & 63);
    const float y0f = (float)(tid >> 4);

    float S = 0.f, Ts = 0.f, mx = 0.f;
    float wxp = 0.f, wyp = 0.f, wxt = 0.f, wyt = 0.f;
    float foc = 0.f, bg = 0.f, plog = 0.f;

    #pragma unroll
    for (int k = 0; k < 4; k++) {
        const int v = tid + k * 256;
        float4 x4 = P[v];
        float4 t4 = T[v];
        float pv[4], tv[4] = {t4.x, t4.y, t4.z, t4.w};
        float xv[4] = {x4.x, x4.y, x4.z, x4.w};

        #pragma unroll
        for (int c = 0; c < 4; c++) {
            float x = xv[c];
            float t = tv[c];
            float h  = 0.5f * fast_tanh(0.5f * x);   // p - 0.5
            float p  = h + 0.5f;
            pv[c] = p;
            float pm = 0.5f + fabsf(h);              // max(p, 1-p) = sigmoid(|x|)
            float lp = __logf(pm);                   // <= 0 ;  -lp = log1p(e^{-|x|})
            // bce = max(x,0) - x*t - lp
            float bce = fmaf(-t, x, fmaxf(x, 0.f) - lp);
            // om = 1 - p_t = p + t*(1-2p)
            float om  = fmaf(t, fmaf(-2.f, p, 1.f), p);
            foc  = fmaf(om * om, bce, foc);
            float p2 = p * p;
            bg   = fmaf(p2, 1.f - t, bg);
            // log p = min(x,0) + lp
            plog = fmaf(p, fminf(x, 0.f) + lp, plog);
            mx   = fmaxf(mx, p);
        }
        // group sums + in-group column weights + row weight
        const float kf = (float)k;
        float gs = (pv[0] + pv[1]) + (pv[2] + pv[3]);
        float gw = fmaf(3.f, pv[3], fmaf(2.f, pv[2], pv[1]));
        S   += gs;
        wxp += gw;
        wyp  = fmaf(kf, gs, wyp);
        float gt = (tv[0] + tv[1]) + (tv[2] + tv[3]);
        float gu = fmaf(3.f, tv[3], fmaf(2.f, tv[2], tv[1]));
        Ts  += gt;
        wxt += gu;
        wyt  = fmaf(kf, gt, wyt);
    }

    // convert to true coordinate-weighted sums (per-thread, before reduction)
    float pxs = fmaf(c0f, S,  wxp);
    float pys = fmaf(y0f, S,  16.f * wyp);
    float txs = fmaf(c0f, Ts, wxt);
    float tys = fmaf(y0f, Ts, 16.f * wyt);

    // warp butterfly reduction: 9 sums + 1 max
    const unsigned FULL = 0xffffffffu;
    #pragma unroll
    for (int o = 16; o; o >>= 1) {
        S    += __shfl_xor_sync(FULL, S,    o);
        Ts   += __shfl_xor_sync(FULL, Ts,   o);
        pxs  += __shfl_xor_sync(FULL, pxs,  o);
        pys  += __shfl_xor_sync(FULL, pys,  o);
        txs  += __shfl_xor_sync(FULL, txs,  o);
        tys  += __shfl_xor_sync(FULL, tys,  o);
        foc  += __shfl_xor_sync(FULL, foc,  o);
        bg   += __shfl_xor_sync(FULL, bg,   o);
        plog += __shfl_xor_sync(FULL, plog, o);
        mx    = fmaxf(mx, __shfl_xor_sync(FULL, mx, o));
    }
    if (lane == 0) {
        warp_red[wid][0] = S;    warp_red[wid][1] = Ts;
        warp_red[wid][2] = pxs;  warp_red[wid][3] = pys;
        warp_red[wid][4] = txs;  warp_red[wid][5] = tys;
        warp_red[wid][6] = foc;  warp_red[wid][7] = bg;
        warp_red[wid][8] = plog; warp_red[wid][9] = mx;
    }
    __syncthreads();

    // cross-warp combine: 8 lanes of warp 0 butterfly-reduce the 8 rows
    if (wid == 0 && lane < 8) {
        float a[10];
        #pragma unroll
        for (int i = 0; i < 10; i++) a[i] = warp_red[lane][i];
        const unsigned M8 = 0x000000ffu;
        #pragma unroll
        for (int o = 4; o; o >>= 1) {
            #pragma unroll
            for (int i = 0; i < 9; i++) a[i] += __shfl_xor_sync(M8, a[i], o);
            a[9] = fmaxf(a[9], __shfl_xor_sync(M8, a[9], o));
        }
        if (lane == 0) {
            float Sp  = a[0] + EPS_V;
            float inv = 1.f / Sp;
            float ent = inv * (a[0] * logf(Sp) - a[8]);
            float ts  = a[1] + EPS_V;
            float px  = a[2] * inv, py = a[3] * inv;
            float tx  = a[4] / ts,  ty = a[5] / ts;
            float dx  = px - tx,    dy = py - ty;
            float coord = sqrtf(dx * dx + dy * dy);
            float conc  = 1.f - a[9];

            g_tile_contrib[tile] =
                (a[6] + BG_W * a[7]) * (1.f / NTOT_F) +
                (SPARSITY_W * ent + CONC_W * conc + COORD_W * coord) * (1.f / (float)NTILES);

            __threadfence();
            unsigned r = atomicAdd(&g_done, 1u);
            is_last = (r == NTILES - 1);
        }
    }
    __syncthreads();

    if (is_last) {
        float v = 0.f;
        for (int i = tid; i < NTILES; i += 256)
            v += g_tile_contrib[i];
        #pragma unroll
        for (int o = 16; o; o >>= 1)
            v += __shfl_xor_sync(FULL, v, o);
        if (lane == 0) warp_red[wid][0] = v;
        __syncthreads();
        if (tid == 0) {
            float s = 0.f;
            #pragma unroll
            for (int w = 0; w < 8; w++) s += warp_red[w][0];
            out[0] = s;
            g_done = 0;   // reset for next graph replay
        }
    }
}

extern "C" void kernel_launch(void* const* d_in, const int* in_sizes, int n_in,
                              void* d_out, int out_size) {
    const float4* pred = (const float4*)d_in[0];
    const float4* tgt  = (const float4*)d_in[1];
    float* out = (float*)d_out;
    loss_kernel<<<NTILES, 256>>>(pred, tgt, out);
}